// round 1
// baseline (speedup 1.0000x reference)
#include <cuda_runtime.h>
#include <math.h>
#include <limits.h>

// Problem constants
#define CIN   256
#define COUT  64
#define KINST 1024
#define HW    80000   // 200*400
#define SIMT  0.9f

// ---------------- scratch (device globals; no allocation allowed) ----------
__device__ float g_mw[KINST * COUT];       // 256 KB
__device__ float g_a[KINST * COUT];        // 256 KB
__device__ unsigned char g_label[KINST * KINST];   // 1 MB  (row-major, i fastest over j)
__device__ unsigned char g_labelT[KINST * KINST];  // 1 MB  (column-major copy: [j][i])
__device__ int   g_pos2[KINST];
__device__ unsigned char g_keep[KINST];
__device__ float g_merged[KINST * COUT];   // 256 KB

// ---------------- kernel A: mw = feat^T @ W^T + b ; a = normalize(mw) ------
__global__ void k_mw(const float* __restrict__ feat,   // (CIN, KINST) : idx_feat[0,:,:,0]
                     const float* __restrict__ W,      // (COUT, CIN)
                     const float* __restrict__ b)
{
    int k = blockIdx.x;          // instance
    int c = threadIdx.x;         // 64 threads = output channel
    __shared__ float f[CIN];
    for (int j = c; j < CIN; j += COUT) f[j] = feat[j * KINST + k];
    __syncthreads();

    const float* wr = W + c * CIN;
    float s = 0.f;
    #pragma unroll 8
    for (int ci = 0; ci < CIN; ci++) s += f[ci] * wr[ci];
    s += b[c];

    __shared__ float red[COUT];
    red[c] = s * s;
    __syncthreads();
    for (int off = 32; off > 0; off >>= 1) {
        if (c < off) red[c] += red[c + off];
        __syncthreads();
    }
    float nrm = sqrtf(red[0]);
    float inv = 1.0f / fmaxf(nrm, 1e-8f);
    g_mw[k * COUT + c] = s;
    g_a [k * COUT + c] = s * inv;
}

// ---------------- kernel B: label = triu(sim>=T) & class-match ------------
#define TI 8
__global__ void k_label(const int* __restrict__ cate)
{
    int i0 = blockIdx.x * TI;
    __shared__ float as[TI][COUT];
    __shared__ int   cs[TI];
    int tid = threadIdx.x;   // 256
    for (int t = tid; t < TI * COUT; t += 256)
        as[t / COUT][t % COUT] = g_a[(i0 + t / COUT) * COUT + (t % COUT)];
    if (tid < TI) cs[tid] = cate[i0 + tid];
    __syncthreads();

    for (int j = tid; j < KINST; j += 256) {
        float sim[TI];
        #pragma unroll
        for (int r = 0; r < TI; r++) sim[r] = 0.f;
        int cj = cate[j];
        const float* aj = g_a + j * COUT;
        for (int c = 0; c < COUT; c++) {
            float av = aj[c];
            #pragma unroll
            for (int r = 0; r < TI; r++) sim[r] += as[r][c] * av;
        }
        #pragma unroll
        for (int r = 0; r < TI; r++) {
            int i = i0 + r;
            unsigned char L = (j >= i) && (sim[r] >= SIMT) && (cj == cs[r]);
            g_label [i * KINST + j] = L;
            g_labelT[j * KINST + i] = L;
        }
    }
}

// ---------------- kernel C: per column j, index of 2nd label; keep --------
__global__ void k_pos2()
{
    int j = blockIdx.x;
    __shared__ int first, second;
    if (threadIdx.x == 0) { first = INT_MAX; second = INT_MAX; }
    __syncthreads();
    const unsigned char* col = g_labelT + j * KINST;
    for (int i = threadIdx.x; i < KINST; i += blockDim.x)
        if (col[i]) atomicMin(&first, i);
    __syncthreads();
    for (int i = threadIdx.x; i < KINST; i += blockDim.x)
        if (col[i] && i > first) atomicMin(&second, i);
    __syncthreads();
    if (threadIdx.x == 0) {
        g_pos2[j] = second;                 // cum[i][j] == (i < second)
        g_keep[j] = (second > j) ? 1 : 0;   // keep[j] = cum[j][j]
    }
}

// ---------------- kernel D: merged = lm @ mw / ln --------------------------
__global__ void k_merged()
{
    int i = blockIdx.x;
    int c = threadIdx.x;  // 64
    float acc = 0.f;
    int cnt = 0;
    if (g_keep[i]) {
        const unsigned char* row = g_label + i * KINST;
        for (int j = i; j < KINST; j++) {           // label is upper-triangular
            if (row[j] && i < g_pos2[j]) {
                acc += g_mw[j * COUT + c];
                cnt++;
            }
        }
    }
    float d = (cnt > 0) ? (float)cnt : 1.0f;
    g_merged[i * COUT + c] = acc / d;
}

// ---------------- kernel F: inst = merged(1024x64) @ x(64x80000) ----------
// Tile 64(M) x 64(N), K=64 in one shot. 256 threads, 4x4 register tile.
#define LDA 68   // padded stride for transposed merged tile (keeps 16B alignment)
__global__ void __launch_bounds__(256, 4)
k_inst(const float* __restrict__ x, float* __restrict__ out)
{
    __shared__ float msT[COUT * LDA];     // [c][m] transposed, padded
    __shared__ float xs[COUT * 64];       // [c][p]
    int bn = blockIdx.x;                  // N tile (80000/64 = 1250)
    int bm = blockIdx.y;                  // M tile (1024/64 = 16)
    int tid = threadIdx.x;

    for (int idx = tid; idx < 4096; idx += 256) {
        int m = idx >> 6, c = idx & 63;
        msT[c * LDA + m] = g_merged[(bm * 64 + m) * COUT + c];
    }
    const float* xg = x + bn * 64;
    for (int idx = tid; idx < 4096; idx += 256) {
        int c = idx >> 6, p = idx & 63;
        xs[c * 64 + p] = xg[c * HW + p];
    }
    __syncthreads();

    int ty = tid >> 4, tx = tid & 15;
    int m0 = ty * 4, p0 = tx * 4;

    float4 acc0 = {0,0,0,0}, acc1 = {0,0,0,0}, acc2 = {0,0,0,0}, acc3 = {0,0,0,0};
    #pragma unroll
    for (int c = 0; c < 64; c++) {
        float4 av = *(const float4*)&msT[c * LDA + m0];
        float4 bv = *(const float4*)&xs[c * 64 + p0];
        acc0.x += av.x * bv.x; acc0.y += av.x * bv.y; acc0.z += av.x * bv.z; acc0.w += av.x * bv.w;
        acc1.x += av.y * bv.x; acc1.y += av.y * bv.y; acc1.z += av.y * bv.z; acc1.w += av.y * bv.w;
        acc2.x += av.z * bv.x; acc2.y += av.z * bv.y; acc2.z += av.z * bv.z; acc2.w += av.z * bv.w;
        acc3.x += av.w * bv.x; acc3.y += av.w * bv.y; acc3.z += av.w * bv.z; acc3.w += av.w * bv.w;
    }

    float* og = out + (size_t)(bm * 64 + m0) * HW + bn * 64 + p0;
    *(float4*)&og[0]          = acc0;
    *(float4*)&og[(size_t)HW] = acc1;
    *(float4*)&og[(size_t)2*HW] = acc2;
    *(float4*)&og[(size_t)3*HW] = acc3;
}

// ---------------- kernel G: tail outputs (keep, cate, score as f32) -------
__global__ void k_tail(const int* __restrict__ cate,
                       const float* __restrict__ score,
                       float* __restrict__ out)
{
    int j = blockIdx.x * blockDim.x + threadIdx.x;
    if (j < KINST) {
        out[(size_t)KINST * HW + j]             = g_keep[j] ? 1.0f : 0.0f;
        out[(size_t)KINST * HW + KINST + j]     = (float)cate[j];
        out[(size_t)KINST * HW + 2 * KINST + j] = score[j];
    }
}

// ---------------------------------------------------------------------------
extern "C" void kernel_launch(void* const* d_in, const int* in_sizes, int n_in,
                              void* d_out, int out_size)
{
    // metadata order: x, idx_feat, pred_cate, pred_score, W, b, n, h, w
    const float* x        = (const float*)d_in[0];   // (1,64,80000)
    const float* idx_feat = (const float*)d_in[1];   // (1,256,1024,1)
    const int*   cate     = (const int*)  d_in[2];   // (1024,)
    const float* score    = (const float*)d_in[3];   // (1024,)
    const float* W        = (const float*)d_in[4];   // (64,256)
    const float* b        = (const float*)d_in[5];   // (64,)
    float* out = (float*)d_out;

    k_mw<<<KINST, COUT>>>(idx_feat, W, b);
    k_label<<<KINST / TI, 256>>>(cate);
    k_pos2<<<KINST, 256>>>();
    k_merged<<<KINST, COUT>>>();

    dim3 grid(HW / 64, KINST / 64);       // (1250, 16)
    k_inst<<<grid, 256>>>(x, out);

    if (out_size >= KINST * HW + 3 * KINST)
        k_tail<<<4, 256>>>(cate, score, out);
}

// round 3
// speedup vs baseline: 1.8893x; 1.8893x over previous
#include <cuda_runtime.h>
#include <math.h>
#include <limits.h>
#include <stdint.h>

// Problem constants
#define CIN   256
#define COUT  64
#define KINST 1024
#define HW    80000   // 200*400
#define SIMT  0.9f

// ---------------- scratch (device globals; no allocation allowed) ----------
__device__ float g_mw[KINST * COUT];
__device__ float g_a[KINST * COUT];
__device__ unsigned char g_label[KINST * KINST];
__device__ unsigned char g_labelT[KINST * KINST];
__device__ int   g_pos2[KINST];
__device__ unsigned char g_keep[KINST];
__device__ float g_merged[KINST * COUT];

// ---------------- helpers ---------------------------------------------------
__device__ __forceinline__ uint32_t f2tf32(float f) {
    uint32_t r;
    asm("cvt.rna.tf32.f32 %0, %1;" : "=r"(r) : "f"(f));
    return r;
}
__device__ __forceinline__ void mma_tf32(float c[4],
                                         uint32_t a0, uint32_t a1, uint32_t a2, uint32_t a3,
                                         uint32_t b0, uint32_t b1) {
    asm volatile(
        "mma.sync.aligned.m16n8k8.row.col.f32.tf32.tf32.f32 "
        "{%0,%1,%2,%3}, {%4,%5,%6,%7}, {%8,%9}, {%0,%1,%2,%3};"
        : "+f"(c[0]), "+f"(c[1]), "+f"(c[2]), "+f"(c[3])
        : "r"(a0), "r"(a1), "r"(a2), "r"(a3), "r"(b0), "r"(b1));
}

// ---------------- kernel A: mw = feat^T @ W^T + b ; a = normalize(mw) ------
__global__ void k_mw(const float* __restrict__ feat,
                     const float* __restrict__ W,
                     const float* __restrict__ b)
{
    int k = blockIdx.x;
    int c = threadIdx.x;
    __shared__ float f[CIN];
    for (int j = c; j < CIN; j += COUT) f[j] = feat[j * KINST + k];
    __syncthreads();

    const float* wr = W + c * CIN;
    float s = 0.f;
    #pragma unroll 8
    for (int ci = 0; ci < CIN; ci++) s += f[ci] * wr[ci];
    s += b[c];

    __shared__ float red[COUT];
    red[c] = s * s;
    __syncthreads();
    for (int off = 32; off > 0; off >>= 1) {
        if (c < off) red[c] += red[c + off];
        __syncthreads();
    }
    float inv = 1.0f / fmaxf(sqrtf(red[0]), 1e-8f);
    g_mw[k * COUT + c] = s;
    g_a [k * COUT + c] = s * inv;
}

// ---------------- kernel B: label = triu(sim>=T) & class-match -------------
#define TI 8
__global__ void k_label(const int* __restrict__ cate)
{
    int i0 = blockIdx.x * TI;
    __shared__ float as[TI][COUT];
    __shared__ int   cs[TI];
    int tid = threadIdx.x;
    for (int t = tid; t < TI * COUT; t += 256)
        as[t / COUT][t % COUT] = g_a[(i0 + t / COUT) * COUT + (t % COUT)];
    if (tid < TI) cs[tid] = cate[i0 + tid];
    __syncthreads();

    for (int j = tid; j < KINST; j += 256) {
        float sim[TI];
        #pragma unroll
        for (int r = 0; r < TI; r++) sim[r] = 0.f;
        int cj = cate[j];
        const float* aj = g_a + j * COUT;
        for (int c = 0; c < COUT; c++) {
            float av = aj[c];
            #pragma unroll
            for (int r = 0; r < TI; r++) sim[r] += as[r][c] * av;
        }
        #pragma unroll
        for (int r = 0; r < TI; r++) {
            int i = i0 + r;
            unsigned char L = (j >= i) && (sim[r] >= SIMT) && (cj == cs[r]);
            g_label [i * KINST + j] = L;
            g_labelT[j * KINST + i] = L;
        }
    }
}

// ---------------- kernel C: pos2 / keep -------------------------------------
__global__ void k_pos2()
{
    int j = blockIdx.x;
    __shared__ int first, second;
    if (threadIdx.x == 0) { first = INT_MAX; second = INT_MAX; }
    __syncthreads();
    const unsigned char* col = g_labelT + j * KINST;
    for (int i = threadIdx.x; i < KINST; i += blockDim.x)
        if (col[i]) atomicMin(&first, i);
    __syncthreads();
    for (int i = threadIdx.x; i < KINST; i += blockDim.x)
        if (col[i] && i > first) atomicMin(&second, i);
    __syncthreads();
    if (threadIdx.x == 0) {
        g_pos2[j] = second;
        g_keep[j] = (second > j) ? 1 : 0;
    }
}

// ---------------- kernel D: merged = lm @ mw / ln (compacted) --------------
__global__ void k_merged()
{
    int i = blockIdx.x;
    int tid = threadIdx.x;
    __shared__ int list[KINST];
    __shared__ int cnt;
    if (tid == 0) cnt = 0;
    __syncthreads();
    if (g_keep[i]) {
        const unsigned char* row = g_label + i * KINST;
        for (int j = i + tid; j < KINST; j += 256)
            if (row[j] && i < g_pos2[j]) list[atomicAdd(&cnt, 1)] = j;
    }
    __syncthreads();
    int m = cnt;
    if (tid < COUT) {
        float acc = 0.f;
        for (int t = 0; t < m; t++) acc += g_mw[list[t] * COUT + tid];
        g_merged[i * COUT + tid] = acc / (m > 0 ? (float)m : 1.0f);
    }
}

// ---------------- kernel F: inst = merged @ x via mma.sync tf32 -------------
// Block tile: 128(M) x 128(N), K=64 single phase. 256 threads = 8 warps (2x4).
// Warp tile: 64(M) x 32(N) via m16n8k8 -> 4 mfrag x 4 nfrag.
#define BM 128
#define BN 128
#define BK 64
#define ASTR 68    // A smem row stride (floats): bank = g*4+c -> conflict-free
#define BSTR 136   // B smem row stride (floats): bank = k*8+n -> conflict-free
#define ASZ (BM * ASTR)          // 8704 floats
#define SMEM_FLOATS (ASZ + BK * BSTR)   // 8704 + 8704 = 17408 floats = 69632 B

__global__ void __launch_bounds__(256, 2)
k_inst_mma(const float* __restrict__ x, float* __restrict__ out)
{
    extern __shared__ float smf[];
    uint32_t* as = (uint32_t*)smf;          // A tile [m][k], tf32 bits
    uint32_t* bs = (uint32_t*)(smf + ASZ);  // B tile [k][n], tf32 bits

    int tid = threadIdx.x;
    int wid = tid >> 5, lid = tid & 31;
    int g = lid >> 2, c4 = lid & 3;
    int m0 = blockIdx.y * BM;
    int n0 = blockIdx.x * BN;

    // Load A (128x64) -> smem as tf32, padded stride
    for (int idx = tid; idx < BM * BK / 4; idx += 256) {
        int m = idx >> 4;
        int k4 = (idx & 15) * 4;
        float4 v = *(const float4*)&g_merged[(m0 + m) * COUT + k4];
        uint32_t* d = &as[m * ASTR + k4];
        d[0] = f2tf32(v.x); d[1] = f2tf32(v.y); d[2] = f2tf32(v.z); d[3] = f2tf32(v.w);
    }
    // Load B (64x128) = x[k][n0+n] -> smem as tf32
    for (int idx = tid; idx < BK * BN / 4; idx += 256) {
        int k = idx >> 5;
        int n4 = (idx & 31) * 4;
        float4 v = *(const float4*)&x[(size_t)k * HW + n0 + n4];
        uint32_t* d = &bs[k * BSTR + n4];
        d[0] = f2tf32(v.x); d[1] = f2tf32(v.y); d[2] = f2tf32(v.z); d[3] = f2tf32(v.w);
    }
    __syncthreads();

    int wm = (wid >> 2) * 64;    // 0 or 64
    int wn = (wid & 3) * 32;     // 0,32,64,96

    float acc[4][4][4];
    #pragma unroll
    for (int mf = 0; mf < 4; mf++)
        #pragma unroll
        for (int nf = 0; nf < 4; nf++)
            #pragma unroll
            for (int q = 0; q < 4; q++) acc[mf][nf][q] = 0.f;

    #pragma unroll
    for (int s = 0; s < 8; s++) {
        int kk = s * 8;
        uint32_t a[4][4];
        #pragma unroll
        for (int mf = 0; mf < 4; mf++) {
            int base = (wm + mf * 16 + g) * ASTR + kk + c4;
            a[mf][0] = as[base];
            a[mf][1] = as[base + 8 * ASTR];
            a[mf][2] = as[base + 4];
            a[mf][3] = as[base + 8 * ASTR + 4];
        }
        #pragma unroll
        for (int nf = 0; nf < 4; nf++) {
            int bb = (kk + c4) * BSTR + wn + nf * 8 + g;
            uint32_t b0 = bs[bb];
            uint32_t b1 = bs[bb + 4 * BSTR];
            #pragma unroll
            for (int mf = 0; mf < 4; mf++)
                mma_tf32(acc[mf][nf], a[mf][0], a[mf][1], a[mf][2], a[mf][3], b0, b1);
        }
    }

    // Epilogue: c0 (row g, col 2c4), c1 (col+1), c2/c3 (row g+8)
    #pragma unroll
    for (int mf = 0; mf < 4; mf++) {
        size_t r0 = (size_t)(m0 + wm + mf * 16 + g) * HW + n0;
        #pragma unroll
        for (int nf = 0; nf < 4; nf++) {
            int col = wn + nf * 8 + 2 * c4;
            *(float2*)&out[r0 + col]            = make_float2(acc[mf][nf][0], acc[mf][nf][1]);
            *(float2*)&out[r0 + 8 * HW + col]   = make_float2(acc[mf][nf][2], acc[mf][nf][3]);
        }
    }
}

// ---------------- kernel G: tail outputs ------------------------------------
__global__ void k_tail(const int* __restrict__ cate,
                       const float* __restrict__ score,
                       float* __restrict__ out)
{
    int j = blockIdx.x * blockDim.x + threadIdx.x;
    if (j < KINST) {
        out[(size_t)KINST * HW + j]             = g_keep[j] ? 1.0f : 0.0f;
        out[(size_t)KINST * HW + KINST + j]     = (float)cate[j];
        out[(size_t)KINST * HW + 2 * KINST + j] = score[j];
    }
}

// ---------------------------------------------------------------------------
extern "C" void kernel_launch(void* const* d_in, const int* in_sizes, int n_in,
                              void* d_out, int out_size)
{
    const float* x        = (const float*)d_in[0];
    const float* idx_feat = (const float*)d_in[1];
    const int*   cate     = (const int*)  d_in[2];
    const float* score    = (const float*)d_in[3];
    const float* W        = (const float*)d_in[4];
    const float* b        = (const float*)d_in[5];
    float* out = (float*)d_out;

    k_mw<<<KINST, COUT>>>(idx_feat, W, b);
    k_label<<<KINST / TI, 256>>>(cate);
    k_pos2<<<KINST, 256>>>();
    k_merged<<<KINST, 256>>>();

    static bool attr_set = false;
    if (!attr_set) {
        cudaFuncSetAttribute(k_inst_mma, cudaFuncAttributeMaxDynamicSharedMemorySize,
                             SMEM_FLOATS * 4);
        attr_set = true;
    }
    dim3 grid(HW / BN, KINST / BM);   // (625, 8)
    k_inst_mma<<<grid, 256, SMEM_FLOATS * 4>>>(x, out);

    if (out_size >= KINST * HW + 3 * KINST)
        k_tail<<<4, 256>>>(cate, score, out);
}

// round 4
// speedup vs baseline: 2.7360x; 1.4482x over previous
#include <cuda_runtime.h>
#include <cuda_fp16.h>
#include <math.h>
#include <limits.h>
#include <stdint.h>

// Problem constants
#define CIN   256
#define COUT  64
#define KINST 1024
#define HW    80000   // 200*400
#define SIMT  0.9f

// ---------------- scratch (device globals; no allocation allowed) ----------
__device__ float g_mw[KINST * COUT];
__device__ float g_a[KINST * COUT];
__device__ unsigned char g_label[KINST * KINST];
__device__ unsigned char g_labelT[KINST * KINST];
__device__ int   g_pos2[KINST];
__device__ unsigned char g_keep[KINST];
__device__ float g_merged[KINST * COUT];

// ---------------- PTX helpers ----------------------------------------------
__device__ __forceinline__ uint32_t smem_u32(const void* p) {
    uint32_t a;
    asm("{ .reg .u64 t; cvta.to.shared.u64 t, %1; cvt.u32.u64 %0, t; }" : "=r"(a) : "l"(p));
    return a;
}
__device__ __forceinline__ void ldsm_x4(uint32_t r[4], uint32_t addr) {
    asm volatile("ldmatrix.sync.aligned.m8n8.x4.shared.b16 {%0,%1,%2,%3}, [%4];"
                 : "=r"(r[0]), "=r"(r[1]), "=r"(r[2]), "=r"(r[3]) : "r"(addr));
}
__device__ __forceinline__ void ldsm_x2t(uint32_t r[2], uint32_t addr) {
    asm volatile("ldmatrix.sync.aligned.m8n8.x2.trans.shared.b16 {%0,%1}, [%2];"
                 : "=r"(r[0]), "=r"(r[1]) : "r"(addr));
}
__device__ __forceinline__ void mma_f16(float c[4], const uint32_t a[4], const uint32_t b[2]) {
    asm volatile(
        "mma.sync.aligned.m16n8k16.row.col.f32.f16.f16.f32 "
        "{%0,%1,%2,%3}, {%4,%5,%6,%7}, {%8,%9}, {%0,%1,%2,%3};"
        : "+f"(c[0]), "+f"(c[1]), "+f"(c[2]), "+f"(c[3])
        : "r"(a[0]), "r"(a[1]), "r"(a[2]), "r"(a[3]), "r"(b[0]), "r"(b[1]));
}

// ---------------- kernel A: mw = feat^T @ W^T + b ; a = normalize ----------
// Block: 16 instances, 256 threads. W staged transposed in padded smem.
#define MWI 16
#define WSTR 65
#define FSTR 17
__global__ void k_mw(const float* __restrict__ feat,   // (CIN, KINST)
                     const float* __restrict__ W,      // (COUT, CIN)
                     const float* __restrict__ b)
{
    extern __shared__ float sm[];
    float* Wsm = sm;                     // [CIN][WSTR]
    float* ft  = sm + CIN * WSTR;        // [CIN][FSTR]
    float* red = ft + CIN * FSTR;        // [8 warps][4]

    int tid = threadIdx.x;
    int k0 = blockIdx.x * MWI;

    // W transpose-load: read W[c][ci..] coalesced, write Wsm[ci][c]
    for (int idx = tid; idx < COUT * (CIN / 4); idx += 256) {
        int c = idx >> 6;
        int ci4 = (idx & 63) * 4;
        float4 v = *(const float4*)&W[c * CIN + ci4];
        Wsm[(ci4 + 0) * WSTR + c] = v.x;
        Wsm[(ci4 + 1) * WSTR + c] = v.y;
        Wsm[(ci4 + 2) * WSTR + c] = v.z;
        Wsm[(ci4 + 3) * WSTR + c] = v.w;
    }
    // feat tile: [CIN][MWI]
    for (int idx = tid; idx < CIN * (MWI / 4); idx += 256) {
        int ci = idx >> 2;
        int kk4 = (idx & 3) * 4;
        float4 v = *(const float4*)&feat[ci * KINST + k0 + kk4];
        ft[ci * FSTR + kk4 + 0] = v.x;
        ft[ci * FSTR + kk4 + 1] = v.y;
        ft[ci * FSTR + kk4 + 2] = v.z;
        ft[ci * FSTR + kk4 + 3] = v.w;
    }
    __syncthreads();

    int c = tid & 63, tg = tid >> 6;     // instance kk = tg + 4q
    float s[4] = {0.f, 0.f, 0.f, 0.f};
    #pragma unroll 4
    for (int ci = 0; ci < CIN; ci++) {
        float w = Wsm[ci * WSTR + c];
        const float* fr = &ft[ci * FSTR + tg];
        s[0] += fr[0] * w;
        s[1] += fr[4] * w;
        s[2] += fr[8] * w;
        s[3] += fr[12] * w;
    }
    float bc = b[c];
    #pragma unroll
    for (int q = 0; q < 4; q++) s[q] += bc;

    int warp = tid >> 5;
    #pragma unroll
    for (int q = 0; q < 4; q++) {
        float v = s[q] * s[q];
        #pragma unroll
        for (int o = 16; o > 0; o >>= 1) v += __shfl_xor_sync(0xffffffffu, v, o);
        if ((tid & 31) == 0) red[warp * 4 + q] = v;
    }
    __syncthreads();
    #pragma unroll
    for (int q = 0; q < 4; q++) {
        float tot = red[(tg * 2) * 4 + q] + red[(tg * 2 + 1) * 4 + q];
        float inv = 1.0f / fmaxf(sqrtf(tot), 1e-8f);
        int k = k0 + tg + 4 * q;
        g_mw[k * COUT + c] = s[q];
        g_a [k * COUT + c] = s[q] * inv;
    }
}
#define MW_SMEM ((CIN * WSTR + CIN * FSTR + 32) * 4)

// ---------------- kernel B: label = triu(sim>=T) & class-match -------------
// Block: 8 i-rows x all j; j staged in padded smem chunks of 256.
#define TI 8
#define AJSTR 65
__global__ void k_label(const int* __restrict__ cate)
{
    extern __shared__ float sm[];
    float* as  = sm;                     // [TI][COUT]
    float* ajs = sm + TI * COUT;         // [256][AJSTR]
    __shared__ int cs[TI];

    int tid = threadIdx.x;
    int i0 = blockIdx.x * TI;

    for (int idx = tid; idx < TI * COUT; idx += 256)
        as[idx] = g_a[(i0 + (idx >> 6)) * COUT + (idx & 63)];
    if (tid < TI) cs[tid] = cate[i0 + tid];

    for (int chunk = 0; chunk < 4; chunk++) {
        int jb = chunk * 256;
        __syncthreads();
        for (int idx = tid; idx < 256 * 16; idx += 256) {
            int j = idx >> 4;
            int c4 = (idx & 15) * 4;
            float4 v = *(const float4*)&g_a[(jb + j) * COUT + c4];
            float* d = &ajs[j * AJSTR + c4];
            d[0] = v.x; d[1] = v.y; d[2] = v.z; d[3] = v.w;
        }
        __syncthreads();

        int j = jb + tid;
        int cj = cate[j];
        float sim[TI];
        #pragma unroll
        for (int r = 0; r < TI; r++) sim[r] = 0.f;
        const float* aj = &ajs[tid * AJSTR];
        #pragma unroll 4
        for (int c = 0; c < COUT; c++) {
            float av = aj[c];
            #pragma unroll
            for (int r = 0; r < TI; r++) sim[r] += as[r * COUT + c] * av;
        }
        #pragma unroll
        for (int r = 0; r < TI; r++) {
            int i = i0 + r;
            unsigned char L = (j >= i) && (sim[r] >= SIMT) && (cj == cs[r]);
            g_label [i * KINST + j] = L;
            g_labelT[j * KINST + i] = L;
        }
    }
}
#define LB_SMEM ((TI * COUT + 256 * AJSTR) * 4)

// ---------------- kernel C: pos2 / keep -------------------------------------
__global__ void k_pos2()
{
    int j = blockIdx.x;
    __shared__ int first, second;
    if (threadIdx.x == 0) { first = INT_MAX; second = INT_MAX; }
    __syncthreads();
    const unsigned char* col = g_labelT + j * KINST;
    for (int i = threadIdx.x; i < KINST; i += blockDim.x)
        if (col[i]) atomicMin(&first, i);
    __syncthreads();
    for (int i = threadIdx.x; i < KINST; i += blockDim.x)
        if (col[i] && i > first) atomicMin(&second, i);
    __syncthreads();
    if (threadIdx.x == 0) {
        g_pos2[j] = second;
        g_keep[j] = (second > j) ? 1 : 0;
    }
}

// ---------------- kernel D: merged = lm @ mw / ln (compacted) --------------
__global__ void k_merged()
{
    int i = blockIdx.x;
    int tid = threadIdx.x;
    __shared__ int list[KINST];
    __shared__ int cnt;
    if (tid == 0) cnt = 0;
    __syncthreads();
    if (g_keep[i]) {
        const unsigned char* row = g_label + i * KINST;
        for (int j = i + tid; j < KINST; j += 256)
            if (row[j] && i < g_pos2[j]) list[atomicAdd(&cnt, 1)] = j;
    }
    __syncthreads();
    int m = cnt;
    if (tid < COUT) {
        float acc = 0.f;
        for (int t = 0; t < m; t++) acc += g_mw[list[t] * COUT + tid];
        g_merged[i * COUT + tid] = acc / (m > 0 ? (float)m : 1.0f);
    }
}

// ---------------- kernel F: inst = merged @ x, fp16 mma + ldmatrix ---------
// Block 128(M) x 128(N), K=64 (4 steps of 16). 256 threads = 8 warps (2x4).
// Warp tile 64x32: 4 mf x 4 nf x m16n8k16.
#define BM 128
#define BN 128
#define ASTRH 72    // A smem stride (halves): 144B rows -> ldmatrix conflict-free
#define BSTRH 136   // B smem stride (halves): 272B rows

__global__ void __launch_bounds__(256, 2)
k_inst_mma(const float* __restrict__ x, float* __restrict__ out)
{
    __shared__ __align__(16) __half as_h[BM * ASTRH];   // 18 KB
    __shared__ __align__(16) __half bs_h[64 * BSTRH];   // 17 KB

    int tid = threadIdx.x;
    int wid = tid >> 5, lid = tid & 31;
    int m0 = blockIdx.y * BM;
    int n0 = blockIdx.x * BN;

    // A: g_merged rows -> fp16 smem [m][k]
    for (int idx = tid; idx < BM * 16; idx += 256) {
        int m = idx >> 4;
        int k4 = (idx & 15) * 4;
        float4 v = *(const float4*)&g_merged[(m0 + m) * COUT + k4];
        *(__half2*)&as_h[m * ASTRH + k4]     = __floats2half2_rn(v.x, v.y);
        *(__half2*)&as_h[m * ASTRH + k4 + 2] = __floats2half2_rn(v.z, v.w);
    }
    // B: x[k][n0..] -> fp16 smem [k][n]
    for (int idx = tid; idx < 64 * 32; idx += 256) {
        int k = idx >> 5;
        int n4 = (idx & 31) * 4;
        float4 v = *(const float4*)&x[(size_t)k * HW + n0 + n4];
        *(__half2*)&bs_h[k * BSTRH + n4]     = __floats2half2_rn(v.x, v.y);
        *(__half2*)&bs_h[k * BSTRH + n4 + 2] = __floats2half2_rn(v.z, v.w);
    }
    __syncthreads();

    int wm = (wid >> 2) * 64;
    int wn = (wid & 3) * 32;
    int lrow = lid & 15, lhalf = lid >> 4;

    uint32_t a_s = smem_u32(as_h);
    uint32_t b_s = smem_u32(bs_h);
    uint32_t a_base = a_s + ((wm + lrow) * ASTRH + lhalf * 8) * 2;
    uint32_t b_base = b_s + (lrow * BSTRH + wn) * 2;

    float acc[4][4][4];
    #pragma unroll
    for (int mf = 0; mf < 4; mf++)
        #pragma unroll
        for (int nf = 0; nf < 4; nf++)
            #pragma unroll
            for (int q = 0; q < 4; q++) acc[mf][nf][q] = 0.f;

    #pragma unroll
    for (int ks = 0; ks < 4; ks++) {
        uint32_t a[4][4], bfr[4][2];
        #pragma unroll
        for (int mf = 0; mf < 4; mf++)
            ldsm_x4(a[mf], a_base + mf * 16 * (ASTRH * 2) + ks * 32);
        #pragma unroll
        for (int nf = 0; nf < 4; nf++)
            ldsm_x2t(bfr[nf], b_base + ks * 16 * (BSTRH * 2) + nf * 16);
        #pragma unroll
        for (int nf = 0; nf < 4; nf++)
            #pragma unroll
            for (int mf = 0; mf < 4; mf++)
                mma_f16(acc[mf][nf], a[mf], bfr[nf]);
    }

    int g = lid >> 2, c4 = lid & 3;
    #pragma unroll
    for (int mf = 0; mf < 4; mf++) {
        size_t r0 = (size_t)(m0 + wm + mf * 16 + g) * HW + n0;
        #pragma unroll
        for (int nf = 0; nf < 4; nf++) {
            int col = wn + nf * 8 + 2 * c4;
            *(float2*)&out[r0 + col]          = make_float2(acc[mf][nf][0], acc[mf][nf][1]);
            *(float2*)&out[r0 + 8 * HW + col] = make_float2(acc[mf][nf][2], acc[mf][nf][3]);
        }
    }
}

// ---------------- kernel G: tail outputs ------------------------------------
__global__ void k_tail(const int* __restrict__ cate,
                       const float* __restrict__ score,
                       float* __restrict__ out)
{
    int j = blockIdx.x * blockDim.x + threadIdx.x;
    if (j < KINST) {
        out[(size_t)KINST * HW + j]             = g_keep[j] ? 1.0f : 0.0f;
        out[(size_t)KINST * HW + KINST + j]     = (float)cate[j];
        out[(size_t)KINST * HW + 2 * KINST + j] = score[j];
    }
}

// ---------------------------------------------------------------------------
extern "C" void kernel_launch(void* const* d_in, const int* in_sizes, int n_in,
                              void* d_out, int out_size)
{
    const float* x        = (const float*)d_in[0];
    const float* idx_feat = (const float*)d_in[1];
    const int*   cate     = (const int*)  d_in[2];
    const float* score    = (const float*)d_in[3];
    const float* W        = (const float*)d_in[4];
    const float* b        = (const float*)d_in[5];
    float* out = (float*)d_out;

    static bool attr_set = false;
    if (!attr_set) {
        cudaFuncSetAttribute(k_mw,    cudaFuncAttributeMaxDynamicSharedMemorySize, MW_SMEM);
        cudaFuncSetAttribute(k_label, cudaFuncAttributeMaxDynamicSharedMemorySize, LB_SMEM);
        attr_set = true;
    }

    k_mw<<<KINST / MWI, 256, MW_SMEM>>>(idx_feat, W, b);
    k_label<<<KINST / TI, 256, LB_SMEM>>>(cate);
    k_pos2<<<KINST, 256>>>();
    k_merged<<<KINST, 256>>>();

    dim3 grid(HW / BN, KINST / BM);   // (625, 8)
    k_inst_mma<<<grid, 256>>>(x, out);

    if (out_size >= KINST * HW + 3 * KINST)
        k_tail<<<4, 256>>>(cate, score, out);
}

// round 5
// speedup vs baseline: 2.7411x; 1.0019x over previous
#include <cuda_runtime.h>
#include <cuda_fp16.h>
#include <math.h>
#include <limits.h>
#include <stdint.h>

// Problem constants
#define CIN   256
#define COUT  64
#define KINST 1024
#define HW    80000   // 200*400
#define SIMT  0.9f

// ---------------- scratch (device globals; no allocation allowed) ----------
__device__ float g_mw[KINST * COUT];
__device__ float g_a[KINST * COUT];
__device__ unsigned char g_label[KINST * KINST];
__device__ unsigned char g_labelT[KINST * KINST];
__device__ int   g_pos2[KINST];
__device__ unsigned char g_keep[KINST];
__device__ float g_merged[KINST * COUT];

// ---------------- PTX helpers ----------------------------------------------
__device__ __forceinline__ uint32_t smem_u32(const void* p) {
    uint32_t a;
    asm("{ .reg .u64 t; cvta.to.shared.u64 t, %1; cvt.u32.u64 %0, t; }" : "=r"(a) : "l"(p));
    return a;
}
__device__ __forceinline__ void ldsm_x4(uint32_t r[4], uint32_t addr) {
    asm volatile("ldmatrix.sync.aligned.m8n8.x4.shared.b16 {%0,%1,%2,%3}, [%4];"
                 : "=r"(r[0]), "=r"(r[1]), "=r"(r[2]), "=r"(r[3]) : "r"(addr));
}
__device__ __forceinline__ void ldsm_x2t(uint32_t r[2], uint32_t addr) {
    asm volatile("ldmatrix.sync.aligned.m8n8.x2.trans.shared.b16 {%0,%1}, [%2];"
                 : "=r"(r[0]), "=r"(r[1]) : "r"(addr));
}
__device__ __forceinline__ void mma_f16(float c[4], const uint32_t a[4], const uint32_t b[2]) {
    asm volatile(
        "mma.sync.aligned.m16n8k16.row.col.f32.f16.f16.f32 "
        "{%0,%1,%2,%3}, {%4,%5,%6,%7}, {%8,%9}, {%0,%1,%2,%3};"
        : "+f"(c[0]), "+f"(c[1]), "+f"(c[2]), "+f"(c[3])
        : "r"(a[0]), "r"(a[1]), "r"(a[2]), "r"(a[3]), "r"(b[0]), "r"(b[1]));
}

// ---------------- kernel A: mw = feat^T @ W^T + b ; a = normalize ----------
// Block: 16 instances, 256 threads. W staged transposed in padded smem.
#define MWI 16
#define WSTR 65
#define FSTR 17
__global__ void k_mw(const float* __restrict__ feat,   // (CIN, KINST)
                     const float* __restrict__ W,      // (COUT, CIN)
                     const float* __restrict__ b)
{
    extern __shared__ float sm[];
    float* Wsm = sm;                     // [CIN][WSTR]
    float* ft  = sm + CIN * WSTR;        // [CIN][FSTR]
    float* red = ft + CIN * FSTR;        // [8 warps][4]

    int tid = threadIdx.x;
    int k0 = blockIdx.x * MWI;

    // W transpose-load: read W[c][ci..] coalesced, write Wsm[ci][c]
    for (int idx = tid; idx < COUT * (CIN / 4); idx += 256) {
        int c = idx >> 6;
        int ci4 = (idx & 63) * 4;
        float4 v = *(const float4*)&W[c * CIN + ci4];
        Wsm[(ci4 + 0) * WSTR + c] = v.x;
        Wsm[(ci4 + 1) * WSTR + c] = v.y;
        Wsm[(ci4 + 2) * WSTR + c] = v.z;
        Wsm[(ci4 + 3) * WSTR + c] = v.w;
    }
    // feat tile: [CIN][MWI]
    for (int idx = tid; idx < CIN * (MWI / 4); idx += 256) {
        int ci = idx >> 2;
        int kk4 = (idx & 3) * 4;
        float4 v = *(const float4*)&feat[ci * KINST + k0 + kk4];
        ft[ci * FSTR + kk4 + 0] = v.x;
        ft[ci * FSTR + kk4 + 1] = v.y;
        ft[ci * FSTR + kk4 + 2] = v.z;
        ft[ci * FSTR + kk4 + 3] = v.w;
    }
    __syncthreads();

    int c = tid & 63, tg = tid >> 6;     // instance kk = tg + 4q
    float s[4] = {0.f, 0.f, 0.f, 0.f};
    #pragma unroll 4
    for (int ci = 0; ci < CIN; ci++) {
        float w = Wsm[ci * WSTR + c];
        const float* fr = &ft[ci * FSTR + tg];
        s[0] += fr[0] * w;
        s[1] += fr[4] * w;
        s[2] += fr[8] * w;
        s[3] += fr[12] * w;
    }
    float bc = b[c];
    #pragma unroll
    for (int q = 0; q < 4; q++) s[q] += bc;

    int warp = tid >> 5;
    #pragma unroll
    for (int q = 0; q < 4; q++) {
        float v = s[q] * s[q];
        #pragma unroll
        for (int o = 16; o > 0; o >>= 1) v += __shfl_xor_sync(0xffffffffu, v, o);
        if ((tid & 31) == 0) red[warp * 4 + q] = v;
    }
    __syncthreads();
    #pragma unroll
    for (int q = 0; q < 4; q++) {
        float tot = red[(tg * 2) * 4 + q] + red[(tg * 2 + 1) * 4 + q];
        float inv = 1.0f / fmaxf(sqrtf(tot), 1e-8f);
        int k = k0 + tg + 4 * q;
        g_mw[k * COUT + c] = s[q];
        g_a [k * COUT + c] = s[q] * inv;
    }
}
#define MW_SMEM ((CIN * WSTR + CIN * FSTR + 32) * 4)

// ---------------- kernel B: label = triu(sim>=T) & class-match -------------
// Block: 8 i-rows x all j; j staged in padded smem chunks of 256.
#define TI 8
#define AJSTR 65
__global__ void k_label(const int* __restrict__ cate)
{
    extern __shared__ float sm[];
    float* as  = sm;                     // [TI][COUT]
    float* ajs = sm + TI * COUT;         // [256][AJSTR]
    __shared__ int cs[TI];

    int tid = threadIdx.x;
    int i0 = blockIdx.x * TI;

    for (int idx = tid; idx < TI * COUT; idx += 256)
        as[idx] = g_a[(i0 + (idx >> 6)) * COUT + (idx & 63)];
    if (tid < TI) cs[tid] = cate[i0 + tid];

    for (int chunk = 0; chunk < 4; chunk++) {
        int jb = chunk * 256;
        __syncthreads();
        for (int idx = tid; idx < 256 * 16; idx += 256) {
            int j = idx >> 4;
            int c4 = (idx & 15) * 4;
            float4 v = *(const float4*)&g_a[(jb + j) * COUT + c4];
            float* d = &ajs[j * AJSTR + c4];
            d[0] = v.x; d[1] = v.y; d[2] = v.z; d[3] = v.w;
        }
        __syncthreads();

        int j = jb + tid;
        int cj = cate[j];
        float sim[TI];
        #pragma unroll
        for (int r = 0; r < TI; r++) sim[r] = 0.f;
        const float* aj = &ajs[tid * AJSTR];
        #pragma unroll 4
        for (int c = 0; c < COUT; c++) {
            float av = aj[c];
            #pragma unroll
            for (int r = 0; r < TI; r++) sim[r] += as[r * COUT + c] * av;
        }
        #pragma unroll
        for (int r = 0; r < TI; r++) {
            int i = i0 + r;
            unsigned char L = (j >= i) && (sim[r] >= SIMT) && (cj == cs[r]);
            g_label [i * KINST + j] = L;
            g_labelT[j * KINST + i] = L;
        }
    }
}
#define LB_SMEM ((TI * COUT + 256 * AJSTR) * 4)

// ---------------- kernel C: pos2 / keep -------------------------------------
__global__ void k_pos2()
{
    int j = blockIdx.x;
    __shared__ int first, second;
    if (threadIdx.x == 0) { first = INT_MAX; second = INT_MAX; }
    __syncthreads();
    const unsigned char* col = g_labelT + j * KINST;
    for (int i = threadIdx.x; i < KINST; i += blockDim.x)
        if (col[i]) atomicMin(&first, i);
    __syncthreads();
    for (int i = threadIdx.x; i < KINST; i += blockDim.x)
        if (col[i] && i > first) atomicMin(&second, i);
    __syncthreads();
    if (threadIdx.x == 0) {
        g_pos2[j] = second;
        g_keep[j] = (second > j) ? 1 : 0;
    }
}

// ---------------- kernel D: merged = lm @ mw / ln (compacted) --------------
__global__ void k_merged()
{
    int i = blockIdx.x;
    int tid = threadIdx.x;
    __shared__ int list[KINST];
    __shared__ int cnt;
    if (tid == 0) cnt = 0;
    __syncthreads();
    if (g_keep[i]) {
        const unsigned char* row = g_label + i * KINST;
        for (int j = i + tid; j < KINST; j += 256)
            if (row[j] && i < g_pos2[j]) list[atomicAdd(&cnt, 1)] = j;
    }
    __syncthreads();
    int m = cnt;
    if (tid < COUT) {
        float acc = 0.f;
        for (int t = 0; t < m; t++) acc += g_mw[list[t] * COUT + tid];
        g_merged[i * COUT + tid] = acc / (m > 0 ? (float)m : 1.0f);
    }
}

// ---------------- kernel F: inst = merged @ x, fp16 mma + ldmatrix ---------
// Block 128(M) x 128(N), K=64 (4 steps of 16). 256 threads = 8 warps (2x4).
// Warp tile 64x32: 4 mf x 4 nf x m16n8k16.
#define BM 128
#define BN 128
#define ASTRH 72    // A smem stride (halves): 144B rows -> ldmatrix conflict-free
#define BSTRH 136   // B smem stride (halves): 272B rows

__global__ void __launch_bounds__(256, 2)
k_inst_mma(const float* __restrict__ x, float* __restrict__ out)
{
    __shared__ __align__(16) __half as_h[BM * ASTRH];   // 18 KB
    __shared__ __align__(16) __half bs_h[64 * BSTRH];   // 17 KB

    int tid = threadIdx.x;
    int wid = tid >> 5, lid = tid & 31;
    int m0 = blockIdx.y * BM;
    int n0 = blockIdx.x * BN;

    // A: g_merged rows -> fp16 smem [m][k]
    for (int idx = tid; idx < BM * 16; idx += 256) {
        int m = idx >> 4;
        int k4 = (idx & 15) * 4;
        float4 v = *(const float4*)&g_merged[(m0 + m) * COUT + k4];
        *(__half2*)&as_h[m * ASTRH + k4]     = __floats2half2_rn(v.x, v.y);
        *(__half2*)&as_h[m * ASTRH + k4 + 2] = __floats2half2_rn(v.z, v.w);
    }
    // B: x[k][n0..] -> fp16 smem [k][n]
    for (int idx = tid; idx < 64 * 32; idx += 256) {
        int k = idx >> 5;
        int n4 = (idx & 31) * 4;
        float4 v = *(const float4*)&x[(size_t)k * HW + n0 + n4];
        *(__half2*)&bs_h[k * BSTRH + n4]     = __floats2half2_rn(v.x, v.y);
        *(__half2*)&bs_h[k * BSTRH + n4 + 2] = __floats2half2_rn(v.z, v.w);
    }
    __syncthreads();

    int wm = (wid >> 2) * 64;
    int wn = (wid & 3) * 32;
    int lrow = lid & 15, lhalf = lid >> 4;

    uint32_t a_s = smem_u32(as_h);
    uint32_t b_s = smem_u32(bs_h);
    uint32_t a_base = a_s + ((wm + lrow) * ASTRH + lhalf * 8) * 2;
    uint32_t b_base = b_s + (lrow * BSTRH + wn) * 2;

    float acc[4][4][4];
    #pragma unroll
    for (int mf = 0; mf < 4; mf++)
        #pragma unroll
        for (int nf = 0; nf < 4; nf++)
            #pragma unroll
            for (int q = 0; q < 4; q++) acc[mf][nf][q] = 0.f;

    #pragma unroll
    for (int ks = 0; ks < 4; ks++) {
        uint32_t a[4][4], bfr[4][2];
        #pragma unroll
        for (int mf = 0; mf < 4; mf++)
            ldsm_x4(a[mf], a_base + mf * 16 * (ASTRH * 2) + ks * 32);
        #pragma unroll
        for (int nf = 0; nf < 4; nf++)
            ldsm_x2t(bfr[nf], b_base + ks * 16 * (BSTRH * 2) + nf * 16);
        #pragma unroll
        for (int nf = 0; nf < 4; nf++)
            #pragma unroll
            for (int mf = 0; mf < 4; mf++)
                mma_f16(acc[mf][nf], a[mf], bfr[nf]);
    }

    int g = lid >> 2, c4 = lid & 3;
    #pragma unroll
    for (int mf = 0; mf < 4; mf++) {
        size_t r0 = (size_t)(m0 + wm + mf * 16 + g) * HW + n0;
        #pragma unroll
        for (int nf = 0; nf < 4; nf++) {
            int col = wn + nf * 8 + 2 * c4;
            *(float2*)&out[r0 + col]          = make_float2(acc[mf][nf][0], acc[mf][nf][1]);
            *(float2*)&out[r0 + 8 * HW + col] = make_float2(acc[mf][nf][2], acc[mf][nf][3]);
        }
    }
}

// ---------------- kernel G: tail outputs ------------------------------------
__global__ void k_tail(const int* __restrict__ cate,
                       const float* __restrict__ score,
                       float* __restrict__ out)
{
    int j = blockIdx.x * blockDim.x + threadIdx.x;
    if (j < KINST) {
        out[(size_t)KINST * HW + j]             = g_keep[j] ? 1.0f : 0.0f;
        out[(size_t)KINST * HW + KINST + j]     = (float)cate[j];
        out[(size_t)KINST * HW + 2 * KINST + j] = score[j];
    }
}

// ---------------------------------------------------------------------------
extern "C" void kernel_launch(void* const* d_in, const int* in_sizes, int n_in,
                              void* d_out, int out_size)
{
    const float* x        = (const float*)d_in[0];
    const float* idx_feat = (const float*)d_in[1];
    const int*   cate     = (const int*)  d_in[2];
    const float* score    = (const float*)d_in[3];
    const float* W        = (const float*)d_in[4];
    const float* b        = (const float*)d_in[5];
    float* out = (float*)d_out;

    static bool attr_set = false;
    if (!attr_set) {
        cudaFuncSetAttribute(k_mw,    cudaFuncAttributeMaxDynamicSharedMemorySize, MW_SMEM);
        cudaFuncSetAttribute(k_label, cudaFuncAttributeMaxDynamicSharedMemorySize, LB_SMEM);
        attr_set = true;
    }

    k_mw<<<KINST / MWI, 256, MW_SMEM>>>(idx_feat, W, b);
    k_label<<<KINST / TI, 256, LB_SMEM>>>(cate);
    k_pos2<<<KINST, 256>>>();
    k_merged<<<KINST, 256>>>();

    dim3 grid(HW / BN, KINST / BM);   // (625, 8)
    k_inst_mma<<<grid, 256>>>(x, out);

    if (out_size >= KINST * HW + 3 * KINST)
        k_tail<<<4, 256>>>(cate, score, out);
}

// round 6
// speedup vs baseline: 3.8353x; 1.3992x over previous
#include <cuda_runtime.h>
#include <cuda_fp16.h>
#include <math.h>
#include <limits.h>
#include <stdint.h>

// Problem constants
#define CIN   256
#define COUT  64
#define KINST 1024
#define HW    80000   // 200*400
#define SIMT  0.9f

// ---------------- scratch (device globals; no allocation allowed) ----------
__device__ float g_mw[KINST * COUT];
__device__ float g_a[KINST * COUT];
__device__ unsigned char g_label[KINST * KINST];
__device__ unsigned char g_labelT[KINST * KINST];
__device__ int   g_pos2[KINST];
__device__ unsigned char g_keep[KINST];
__device__ __half g_merged_h[KINST * COUT];      // fp16 merged (GEMM A)
__device__ __half g_xh[(size_t)COUT * HW];       // fp16 x (GEMM B), 10.24 MB

// ---------------- PTX helpers ----------------------------------------------
__device__ __forceinline__ uint32_t smem_u32(const void* p) {
    uint32_t a;
    asm("{ .reg .u64 t; cvta.to.shared.u64 t, %1; cvt.u32.u64 %0, t; }" : "=r"(a) : "l"(p));
    return a;
}
__device__ __forceinline__ void cp_async16(uint32_t dst, const void* src) {
    asm volatile("cp.async.cg.shared.global [%0], [%1], 16;" :: "r"(dst), "l"(src));
}
__device__ __forceinline__ void cp_commit() {
    asm volatile("cp.async.commit_group;");
}
__device__ __forceinline__ void cp_wait0() {
    asm volatile("cp.async.wait_group 0;");
}
__device__ __forceinline__ void ldsm_x4(uint32_t r[4], uint32_t addr) {
    asm volatile("ldmatrix.sync.aligned.m8n8.x4.shared.b16 {%0,%1,%2,%3}, [%4];"
                 : "=r"(r[0]), "=r"(r[1]), "=r"(r[2]), "=r"(r[3]) : "r"(addr));
}
__device__ __forceinline__ void ldsm_x2t(uint32_t r[2], uint32_t addr) {
    asm volatile("ldmatrix.sync.aligned.m8n8.x2.trans.shared.b16 {%0,%1}, [%2];"
                 : "=r"(r[0]), "=r"(r[1]) : "r"(addr));
}
__device__ __forceinline__ void mma_f16(float c[4], const uint32_t a[4], const uint32_t b[2]) {
    asm volatile(
        "mma.sync.aligned.m16n8k16.row.col.f32.f16.f16.f32 "
        "{%0,%1,%2,%3}, {%4,%5,%6,%7}, {%8,%9}, {%0,%1,%2,%3};"
        : "+f"(c[0]), "+f"(c[1]), "+f"(c[2]), "+f"(c[3])
        : "r"(a[0]), "r"(a[1]), "r"(a[2]), "r"(a[3]), "r"(b[0]), "r"(b[1]));
}

// ---------------- kernel X: x -> fp16 (once) --------------------------------
__global__ void k_xh(const float* __restrict__ x)
{
    size_t i = ((size_t)blockIdx.x * 256 + threadIdx.x) * 4;
    if (i < (size_t)COUT * HW) {
        float4 v = *(const float4*)&x[i];
        *(__half2*)&g_xh[i]     = __floats2half2_rn(v.x, v.y);
        *(__half2*)&g_xh[i + 2] = __floats2half2_rn(v.z, v.w);
    }
}

// ---------------- kernel A: mw = feat^T @ W^T + b ; a = normalize ----------
#define MWI 16
#define WSTR 65
#define FSTR 17
__global__ void k_mw(const float* __restrict__ feat,   // (CIN, KINST)
                     const float* __restrict__ W,      // (COUT, CIN)
                     const float* __restrict__ b)
{
    extern __shared__ float sm[];
    float* Wsm = sm;                     // [CIN][WSTR]
    float* ft  = sm + CIN * WSTR;        // [CIN][FSTR]
    float* red = ft + CIN * FSTR;        // [8 warps][4]

    int tid = threadIdx.x;
    int k0 = blockIdx.x * MWI;

    for (int idx = tid; idx < COUT * (CIN / 4); idx += 256) {
        int c = idx >> 6;
        int ci4 = (idx & 63) * 4;
        float4 v = *(const float4*)&W[c * CIN + ci4];
        Wsm[(ci4 + 0) * WSTR + c] = v.x;
        Wsm[(ci4 + 1) * WSTR + c] = v.y;
        Wsm[(ci4 + 2) * WSTR + c] = v.z;
        Wsm[(ci4 + 3) * WSTR + c] = v.w;
    }
    for (int idx = tid; idx < CIN * (MWI / 4); idx += 256) {
        int ci = idx >> 2;
        int kk4 = (idx & 3) * 4;
        float4 v = *(const float4*)&feat[ci * KINST + k0 + kk4];
        ft[ci * FSTR + kk4 + 0] = v.x;
        ft[ci * FSTR + kk4 + 1] = v.y;
        ft[ci * FSTR + kk4 + 2] = v.z;
        ft[ci * FSTR + kk4 + 3] = v.w;
    }
    __syncthreads();

    int c = tid & 63, tg = tid >> 6;
    float s[4] = {0.f, 0.f, 0.f, 0.f};
    #pragma unroll 4
    for (int ci = 0; ci < CIN; ci++) {
        float w = Wsm[ci * WSTR + c];
        const float* fr = &ft[ci * FSTR + tg];
        s[0] += fr[0] * w;
        s[1] += fr[4] * w;
        s[2] += fr[8] * w;
        s[3] += fr[12] * w;
    }
    float bc = b[c];
    #pragma unroll
    for (int q = 0; q < 4; q++) s[q] += bc;

    int warp = tid >> 5;
    #pragma unroll
    for (int q = 0; q < 4; q++) {
        float v = s[q] * s[q];
        #pragma unroll
        for (int o = 16; o > 0; o >>= 1) v += __shfl_xor_sync(0xffffffffu, v, o);
        if ((tid & 31) == 0) red[warp * 4 + q] = v;
    }
    __syncthreads();
    #pragma unroll
    for (int q = 0; q < 4; q++) {
        float tot = red[(tg * 2) * 4 + q] + red[(tg * 2 + 1) * 4 + q];
        float inv = 1.0f / fmaxf(sqrtf(tot), 1e-8f);
        int k = k0 + tg + 4 * q;
        g_mw[k * COUT + c] = s[q];
        g_a [k * COUT + c] = s[q] * inv;
    }
}
#define MW_SMEM ((CIN * WSTR + CIN * FSTR + 32) * 4)

// ---------------- kernel B: label = triu(sim>=T) & class-match -------------
#define TI 8
#define AJSTR 65
__global__ void k_label(const int* __restrict__ cate)
{
    extern __shared__ float sm[];
    float* as  = sm;                     // [TI][COUT]
    float* ajs = sm + TI * COUT;         // [256][AJSTR]
    __shared__ int cs[TI];

    int tid = threadIdx.x;
    int i0 = blockIdx.x * TI;

    for (int idx = tid; idx < TI * COUT; idx += 256)
        as[idx] = g_a[(i0 + (idx >> 6)) * COUT + (idx & 63)];
    if (tid < TI) cs[tid] = cate[i0 + tid];

    for (int chunk = 0; chunk < 4; chunk++) {
        int jb = chunk * 256;
        __syncthreads();
        for (int idx = tid; idx < 256 * 16; idx += 256) {
            int j = idx >> 4;
            int c4 = (idx & 15) * 4;
            float4 v = *(const float4*)&g_a[(jb + j) * COUT + c4];
            float* d = &ajs[j * AJSTR + c4];
            d[0] = v.x; d[1] = v.y; d[2] = v.z; d[3] = v.w;
        }
        __syncthreads();

        int j = jb + tid;
        int cj = cate[j];
        float sim[TI];
        #pragma unroll
        for (int r = 0; r < TI; r++) sim[r] = 0.f;
        const float* aj = &ajs[tid * AJSTR];
        #pragma unroll 4
        for (int c = 0; c < COUT; c++) {
            float av = aj[c];
            #pragma unroll
            for (int r = 0; r < TI; r++) sim[r] += as[r * COUT + c] * av;
        }
        #pragma unroll
        for (int r = 0; r < TI; r++) {
            int i = i0 + r;
            unsigned char L = (j >= i) && (sim[r] >= SIMT) && (cj == cs[r]);
            g_label [i * KINST + j] = L;
            g_labelT[j * KINST + i] = L;
        }
    }
}
#define LB_SMEM ((TI * COUT + 256 * AJSTR) * 4)

// ---------------- kernel C: pos2 / keep -------------------------------------
__global__ void k_pos2()
{
    int j = blockIdx.x;
    __shared__ int first, second;
    if (threadIdx.x == 0) { first = INT_MAX; second = INT_MAX; }
    __syncthreads();
    const unsigned char* col = g_labelT + j * KINST;
    for (int i = threadIdx.x; i < KINST; i += blockDim.x)
        if (col[i]) atomicMin(&first, i);
    __syncthreads();
    for (int i = threadIdx.x; i < KINST; i += blockDim.x)
        if (col[i] && i > first) atomicMin(&second, i);
    __syncthreads();
    if (threadIdx.x == 0) {
        g_pos2[j] = second;
        g_keep[j] = (second > j) ? 1 : 0;
    }
}

// ---------------- kernel D: merged = lm @ mw / ln -> fp16 ------------------
__global__ void k_merged()
{
    int i = blockIdx.x;
    int tid = threadIdx.x;
    __shared__ int list[KINST];
    __shared__ int cnt;
    if (tid == 0) cnt = 0;
    __syncthreads();
    if (g_keep[i]) {
        const unsigned char* row = g_label + i * KINST;
        for (int j = i + tid; j < KINST; j += 256)
            if (row[j] && i < g_pos2[j]) list[atomicAdd(&cnt, 1)] = j;
    }
    __syncthreads();
    int m = cnt;
    if (tid < COUT) {
        float acc = 0.f;
        for (int t = 0; t < m; t++) acc += g_mw[list[t] * COUT + tid];
        g_merged_h[i * COUT + tid] = __float2half_rn(acc / (m > 0 ? (float)m : 1.0f));
    }
}

// ---------------- kernel F: inst = merged @ x, fp16 mma, pipelined ---------
// Grid (625, 2). Block: N-tile of 128 cols, loops 4 M-tiles of 128 rows.
// B resident in smem; A double-buffered via cp.async.
#define BM 128
#define BN 128
#define MTILES 4
#define ASTRH 72
#define BSTRH 136

__global__ void __launch_bounds__(256, 2)
k_inst_mma(float* __restrict__ out)
{
    __shared__ __align__(16) __half bs_h[64 * BSTRH];        // 17 KB
    __shared__ __align__(16) __half as_h[2][BM * ASTRH];     // 2 x 18 KB

    int tid = threadIdx.x;
    int wid = tid >> 5, lid = tid & 31;
    int n0 = blockIdx.x * BN;
    int mbase = blockIdx.y * (MTILES * BM);

    uint32_t b_s  = smem_u32(bs_h);
    uint32_t a_s0 = smem_u32(as_h[0]);
    uint32_t a_s1 = smem_u32(as_h[1]);

    // Prologue: B tile (64 x 128 fp16) + A tile 0, via cp.async
    #pragma unroll
    for (int t = 0; t < 4; t++) {
        int idx = tid + t * 256;             // 1024 chunks of 16B
        int k = idx >> 4, c16 = idx & 15;
        cp_async16(b_s + (k * BSTRH + c16 * 8) * 2,
                   &g_xh[(size_t)k * HW + n0 + c16 * 8]);
    }
    #pragma unroll
    for (int t = 0; t < 4; t++) {
        int idx = tid + t * 256;             // 1024 chunks of 16B
        int m = idx >> 3, c16 = idx & 7;
        cp_async16(a_s0 + (m * ASTRH + c16 * 8) * 2,
                   &g_merged_h[(mbase + m) * COUT + c16 * 8]);
    }
    cp_commit();

    int wm = (wid >> 2) * 64;
    int wn = (wid & 3) * 32;
    int lrow = lid & 15, lhalf = lid >> 4;
    int g = lid >> 2, c4 = lid & 3;

    uint32_t b_base = b_s + (lrow * BSTRH + wn) * 2;

    for (int mt = 0; mt < MTILES; mt++) {
        cp_wait0();
        __syncthreads();

        // Prefetch next A tile into the other buffer
        if (mt + 1 < MTILES) {
            uint32_t a_nxt = (mt & 1) ? a_s0 : a_s1;
            int mb = mbase + (mt + 1) * BM;
            #pragma unroll
            for (int t = 0; t < 4; t++) {
                int idx = tid + t * 256;
                int m = idx >> 3, c16 = idx & 7;
                cp_async16(a_nxt + (m * ASTRH + c16 * 8) * 2,
                           &g_merged_h[(mb + m) * COUT + c16 * 8]);
            }
            cp_commit();
        }

        uint32_t a_cur = (mt & 1) ? a_s1 : a_s0;
        uint32_t a_base = a_cur + ((wm + lrow) * ASTRH + lhalf * 8) * 2;

        float acc[4][4][4];
        #pragma unroll
        for (int mf = 0; mf < 4; mf++)
            #pragma unroll
            for (int nf = 0; nf < 4; nf++)
                #pragma unroll
                for (int q = 0; q < 4; q++) acc[mf][nf][q] = 0.f;

        #pragma unroll
        for (int ks = 0; ks < 4; ks++) {
            uint32_t a[4][4], bfr[4][2];
            #pragma unroll
            for (int mf = 0; mf < 4; mf++)
                ldsm_x4(a[mf], a_base + mf * 16 * (ASTRH * 2) + ks * 32);
            #pragma unroll
            for (int nf = 0; nf < 4; nf++)
                ldsm_x2t(bfr[nf], b_base + ks * 16 * (BSTRH * 2) + nf * 16);
            #pragma unroll
            for (int nf = 0; nf < 4; nf++)
                #pragma unroll
                for (int mf = 0; mf < 4; mf++)
                    mma_f16(acc[mf][nf], a[mf], bfr[nf]);
        }

        int m0 = mbase + mt * BM;
        #pragma unroll
        for (int mf = 0; mf < 4; mf++) {
            size_t r0 = (size_t)(m0 + wm + mf * 16 + g) * HW + n0;
            #pragma unroll
            for (int nf = 0; nf < 4; nf++) {
                int col = wn + nf * 8 + 2 * c4;
                *(float2*)&out[r0 + col]          = make_float2(acc[mf][nf][0], acc[mf][nf][1]);
                *(float2*)&out[r0 + 8 * HW + col] = make_float2(acc[mf][nf][2], acc[mf][nf][3]);
            }
        }
    }
}

// ---------------- kernel G: tail outputs ------------------------------------
__global__ void k_tail(const int* __restrict__ cate,
                       const float* __restrict__ score,
                       float* __restrict__ out)
{
    int j = blockIdx.x * blockDim.x + threadIdx.x;
    if (j < KINST) {
        out[(size_t)KINST * HW + j]             = g_keep[j] ? 1.0f : 0.0f;
        out[(size_t)KINST * HW + KINST + j]     = (float)cate[j];
        out[(size_t)KINST * HW + 2 * KINST + j] = score[j];
    }
}

// ---------------------------------------------------------------------------
extern "C" void kernel_launch(void* const* d_in, const int* in_sizes, int n_in,
                              void* d_out, int out_size)
{
    const float* x        = (const float*)d_in[0];
    const float* idx_feat = (const float*)d_in[1];
    const int*   cate     = (const int*)  d_in[2];
    const float* score    = (const float*)d_in[3];
    const float* W        = (const float*)d_in[4];
    const float* b        = (const float*)d_in[5];
    float* out = (float*)d_out;

    static bool attr_set = false;
    if (!attr_set) {
        cudaFuncSetAttribute(k_mw,    cudaFuncAttributeMaxDynamicSharedMemorySize, MW_SMEM);
        cudaFuncSetAttribute(k_label, cudaFuncAttributeMaxDynamicSharedMemorySize, LB_SMEM);
        attr_set = true;
    }

    k_xh<<<(COUT * HW / 4 + 255) / 256, 256>>>(x);
    k_mw<<<KINST / MWI, 256, MW_SMEM>>>(idx_feat, W, b);
    k_label<<<KINST / TI, 256, LB_SMEM>>>(cate);
    k_pos2<<<KINST, 256>>>();
    k_merged<<<KINST, 256>>>();

    dim3 grid(HW / BN, KINST / (MTILES * BM));   // (625, 2)
    k_inst_mma<<<grid, 256>>>(out);

    if (out_size >= KINST * HW + 3 * KINST)
        k_tail<<<4, 256>>>(cate, score, out);
}

// round 7
// speedup vs baseline: 4.0178x; 1.0476x over previous
#include <cuda_runtime.h>
#include <cuda_fp16.h>
#include <math.h>
#include <limits.h>
#include <stdint.h>

// Problem constants
#define CIN   256
#define COUT  64
#define KINST 1024
#define HW    80000   // 200*400
#define SIMT  0.9f

// ---------------- scratch (device globals; no allocation allowed) ----------
__device__ float g_mw[KINST * COUT];
__device__ float g_a[KINST * COUT];
__device__ unsigned char g_label[KINST * KINST];
__device__ unsigned char g_labelT[KINST * KINST];
__device__ int   g_pos2[KINST];
__device__ unsigned char g_keep[KINST];
__device__ __half g_merged_h[KINST * COUT];      // fp16 merged (GEMM A)
__device__ __half g_xh[(size_t)COUT * HW];       // fp16 x (GEMM B), 10.24 MB

// ---------------- PTX helpers ----------------------------------------------
__device__ __forceinline__ uint32_t smem_u32(const void* p) {
    uint32_t a;
    asm("{ .reg .u64 t; cvta.to.shared.u64 t, %1; cvt.u32.u64 %0, t; }" : "=r"(a) : "l"(p));
    return a;
}
__device__ __forceinline__ void cp_async16(uint32_t dst, const void* src) {
    asm volatile("cp.async.cg.shared.global [%0], [%1], 16;" :: "r"(dst), "l"(src));
}
__device__ __forceinline__ void cp_commit() {
    asm volatile("cp.async.commit_group;");
}
__device__ __forceinline__ void cp_wait0() {
    asm volatile("cp.async.wait_group 0;");
}
__device__ __forceinline__ void ldsm_x4(uint32_t r[4], uint32_t addr) {
    asm volatile("ldmatrix.sync.aligned.m8n8.x4.shared.b16 {%0,%1,%2,%3}, [%4];"
                 : "=r"(r[0]), "=r"(r[1]), "=r"(r[2]), "=r"(r[3]) : "r"(addr));
}
__device__ __forceinline__ void ldsm_x2t(uint32_t r[2], uint32_t addr) {
    asm volatile("ldmatrix.sync.aligned.m8n8.x2.trans.shared.b16 {%0,%1}, [%2];"
                 : "=r"(r[0]), "=r"(r[1]) : "r"(addr));
}
__device__ __forceinline__ void mma_f16(float c[4], const uint32_t a[4], const uint32_t b[2]) {
    asm volatile(
        "mma.sync.aligned.m16n8k16.row.col.f32.f16.f16.f32 "
        "{%0,%1,%2,%3}, {%4,%5,%6,%7}, {%8,%9}, {%0,%1,%2,%3};"
        : "+f"(c[0]), "+f"(c[1]), "+f"(c[2]), "+f"(c[3])
        : "r"(a[0]), "r"(a[1]), "r"(a[2]), "r"(a[3]), "r"(b[0]), "r"(b[1]));
}

// ---------------- kernel A: mw = feat^T @ W^T + b ; a = normalize ----------
#define MWI 16
#define WSTR 65
#define FSTR 17
__global__ void k_mw(const float* __restrict__ feat,   // (CIN, KINST)
                     const float* __restrict__ W,      // (COUT, CIN)
                     const float* __restrict__ b)
{
    extern __shared__ float sm[];
    float* Wsm = sm;                     // [CIN][WSTR]
    float* ft  = sm + CIN * WSTR;        // [CIN][FSTR]
    float* red = ft + CIN * FSTR;        // [8 warps][4]

    int tid = threadIdx.x;
    int k0 = blockIdx.x * MWI;

    for (int idx = tid; idx < COUT * (CIN / 4); idx += 256) {
        int c = idx >> 6;
        int ci4 = (idx & 63) * 4;
        float4 v = *(const float4*)&W[c * CIN + ci4];
        Wsm[(ci4 + 0) * WSTR + c] = v.x;
        Wsm[(ci4 + 1) * WSTR + c] = v.y;
        Wsm[(ci4 + 2) * WSTR + c] = v.z;
        Wsm[(ci4 + 3) * WSTR + c] = v.w;
    }
    for (int idx = tid; idx < CIN * (MWI / 4); idx += 256) {
        int ci = idx >> 2;
        int kk4 = (idx & 3) * 4;
        float4 v = *(const float4*)&feat[ci * KINST + k0 + kk4];
        ft[ci * FSTR + kk4 + 0] = v.x;
        ft[ci * FSTR + kk4 + 1] = v.y;
        ft[ci * FSTR + kk4 + 2] = v.z;
        ft[ci * FSTR + kk4 + 3] = v.w;
    }
    __syncthreads();

    int c = tid & 63, tg = tid >> 6;
    float s[4] = {0.f, 0.f, 0.f, 0.f};
    #pragma unroll 4
    for (int ci = 0; ci < CIN; ci++) {
        float w = Wsm[ci * WSTR + c];
        const float* fr = &ft[ci * FSTR + tg];
        s[0] += fr[0] * w;
        s[1] += fr[4] * w;
        s[2] += fr[8] * w;
        s[3] += fr[12] * w;
    }
    float bc = b[c];
    #pragma unroll
    for (int q = 0; q < 4; q++) s[q] += bc;

    int warp = tid >> 5;
    #pragma unroll
    for (int q = 0; q < 4; q++) {
        float v = s[q] * s[q];
        #pragma unroll
        for (int o = 16; o > 0; o >>= 1) v += __shfl_xor_sync(0xffffffffu, v, o);
        if ((tid & 31) == 0) red[warp * 4 + q] = v;
    }
    __syncthreads();
    #pragma unroll
    for (int q = 0; q < 4; q++) {
        float tot = red[(tg * 2) * 4 + q] + red[(tg * 2 + 1) * 4 + q];
        float inv = 1.0f / fmaxf(sqrtf(tot), 1e-8f);
        int k = k0 + tg + 4 * q;
        g_mw[k * COUT + c] = s[q];
        g_a [k * COUT + c] = s[q] * inv;
    }
}
#define MW_SMEM ((CIN * WSTR + CIN * FSTR + 32) * 4)

// ---------------- kernel B: label = triu(sim>=T) & class-match -------------
#define TI 8
#define AJSTR 65
__global__ void k_label(const int* __restrict__ cate)
{
    extern __shared__ float sm[];
    float* as  = sm;                     // [TI][COUT]
    float* ajs = sm + TI * COUT;         // [256][AJSTR]
    __shared__ int cs[TI];

    int tid = threadIdx.x;
    int i0 = blockIdx.x * TI;

    for (int idx = tid; idx < TI * COUT; idx += 256)
        as[idx] = g_a[(i0 + (idx >> 6)) * COUT + (idx & 63)];
    if (tid < TI) cs[tid] = cate[i0 + tid];

    for (int chunk = 0; chunk < 4; chunk++) {
        int jb = chunk * 256;
        __syncthreads();
        for (int idx = tid; idx < 256 * 16; idx += 256) {
            int j = idx >> 4;
            int c4 = (idx & 15) * 4;
            float4 v = *(const float4*)&g_a[(jb + j) * COUT + c4];
            float* d = &ajs[j * AJSTR + c4];
            d[0] = v.x; d[1] = v.y; d[2] = v.z; d[3] = v.w;
        }
        __syncthreads();

        int j = jb + tid;
        int cj = cate[j];
        float sim[TI];
        #pragma unroll
        for (int r = 0; r < TI; r++) sim[r] = 0.f;
        const float* aj = &ajs[tid * AJSTR];
        #pragma unroll 4
        for (int c = 0; c < COUT; c++) {
            float av = aj[c];
            #pragma unroll
            for (int r = 0; r < TI; r++) sim[r] += as[r * COUT + c] * av;
        }
        #pragma unroll
        for (int r = 0; r < TI; r++) {
            int i = i0 + r;
            unsigned char L = (j >= i) && (sim[r] >= SIMT) && (cj == cs[r]);
            g_label [i * KINST + j] = L;
            g_labelT[j * KINST + i] = L;
        }
    }
}
#define LB_SMEM ((TI * COUT + 256 * AJSTR) * 4)

// ---------------- kernel C: pos2/keep (warp per column) + fused x->fp16 ----
// Blocks [0,128): pos2 (8 warps = 8 columns each).
// Blocks [128, 128+5000): convert x chunk to fp16.
#define POS2_BLOCKS 128
#define XH_BLOCKS   5000     // 5000 * 256 * 4 = 5.12M elems = COUT*HW
__global__ void k_pos2_xh(const float* __restrict__ x)
{
    if (blockIdx.x >= POS2_BLOCKS) {
        size_t i = ((size_t)(blockIdx.x - POS2_BLOCKS) * 256 + threadIdx.x) * 4;
        float4 v = *(const float4*)&x[i];
        *(__half2*)&g_xh[i]     = __floats2half2_rn(v.x, v.y);
        *(__half2*)&g_xh[i + 2] = __floats2half2_rn(v.z, v.w);
        return;
    }
    int warp = threadIdx.x >> 5, lane = threadIdx.x & 31;
    int j = blockIdx.x * 8 + warp;
    const uint4* col = (const uint4*)(g_labelT + j * KINST) + lane * 2;
    uint4 v0 = col[0], v1 = col[1];
    #define B4(w) (((w) | ((w) >> 7) | ((w) >> 14) | ((w) >> 21)) & 0xFu)
    uint32_t m = B4(v0.x) | (B4(v0.y) << 4) | (B4(v0.z) << 8)  | (B4(v0.w) << 12)
               | (B4(v1.x) << 16) | (B4(v1.y) << 20) | (B4(v1.z) << 24) | (B4(v1.w) << 28);
    #undef B4
    int f1 = 1 << 30, f2 = 1 << 30;
    if (m) {
        f1 = lane * 32 + __ffs(m) - 1;
        uint32_t m2 = m & (m - 1);
        if (m2) f2 = lane * 32 + __ffs(m2) - 1;
    }
    #pragma unroll
    for (int o = 16; o > 0; o >>= 1) {
        int o1 = __shfl_xor_sync(0xffffffffu, f1, o);
        int o2 = __shfl_xor_sync(0xffffffffu, f2, o);
        int n1 = min(f1, o1);
        int n2 = min(max(f1, o1), min(f2, o2));
        f1 = n1; f2 = n2;
    }
    if (lane == 0) {
        g_pos2[j] = f2;                 // index of 2nd label in column j (sentinel if <2)
        g_keep[j] = (f2 > j) ? 1 : 0;
    }
}

// ---------------- kernel D: merged = lm @ mw / ln -> fp16 (+ fused tail) ---
__global__ void k_merged_tail(const int* __restrict__ cate,
                              const float* __restrict__ score,
                              float* __restrict__ out)
{
    if (blockIdx.x >= KINST) {
        int j = (blockIdx.x - KINST) * 256 + threadIdx.x;
        if (j < KINST) {
            out[(size_t)KINST * HW + j]             = g_keep[j] ? 1.0f : 0.0f;
            out[(size_t)KINST * HW + KINST + j]     = (float)cate[j];
            out[(size_t)KINST * HW + 2 * KINST + j] = score[j];
        }
        return;
    }
    int i = blockIdx.x;
    int tid = threadIdx.x;
    __shared__ int list[KINST];
    __shared__ int cnt;
    if (tid == 0) cnt = 0;
    __syncthreads();
    if (g_keep[i]) {
        const unsigned char* row = g_label + i * KINST;
        for (int j = i + tid; j < KINST; j += 256)
            if (row[j] && i < g_pos2[j]) list[atomicAdd(&cnt, 1)] = j;
    }
    __syncthreads();
    int m = cnt;
    if (tid < COUT) {
        float acc = 0.f;
        for (int t = 0; t < m; t++) acc += g_mw[list[t] * COUT + tid];
        g_merged_h[i * COUT + tid] = __float2half_rn(acc / (m > 0 ? (float)m : 1.0f));
    }
}

// ---------------- kernel F: inst = merged @ x, fp16 mma, pipelined ---------
// Grid (625, 4). Block: N-tile of 128 cols, loops 2 M-tiles of 128 rows.
// B resident in smem; A double-buffered via cp.async.
#define BM 128
#define BN 128
#define MTILES 2
#define ASTRH 72
#define BSTRH 136

__global__ void __launch_bounds__(256, 2)
k_inst_mma(float* __restrict__ out)
{
    __shared__ __align__(16) __half bs_h[64 * BSTRH];        // 17 KB
    __shared__ __align__(16) __half as_h[2][BM * ASTRH];     // 2 x 18 KB

    int tid = threadIdx.x;
    int wid = tid >> 5, lid = tid & 31;
    int n0 = blockIdx.x * BN;
    int mbase = blockIdx.y * (MTILES * BM);

    uint32_t b_s  = smem_u32(bs_h);
    uint32_t a_s0 = smem_u32(as_h[0]);
    uint32_t a_s1 = smem_u32(as_h[1]);

    // Prologue: B tile (64 x 128 fp16) + A tile 0, via cp.async
    #pragma unroll
    for (int t = 0; t < 4; t++) {
        int idx = tid + t * 256;             // 1024 chunks of 16B
        int k = idx >> 4, c16 = idx & 15;
        cp_async16(b_s + (k * BSTRH + c16 * 8) * 2,
                   &g_xh[(size_t)k * HW + n0 + c16 * 8]);
    }
    #pragma unroll
    for (int t = 0; t < 4; t++) {
        int idx = tid + t * 256;             // 1024 chunks of 16B
        int m = idx >> 3, c16 = idx & 7;
        cp_async16(a_s0 + (m * ASTRH + c16 * 8) * 2,
                   &g_merged_h[(mbase + m) * COUT + c16 * 8]);
    }
    cp_commit();

    int wm = (wid >> 2) * 64;
    int wn = (wid & 3) * 32;
    int lrow = lid & 15, lhalf = lid >> 4;
    int g = lid >> 2, c4 = lid & 3;

    uint32_t b_base = b_s + (lrow * BSTRH + wn) * 2;

    for (int mt = 0; mt < MTILES; mt++) {
        cp_wait0();
        __syncthreads();

        if (mt + 1 < MTILES) {
            uint32_t a_nxt = (mt & 1) ? a_s0 : a_s1;
            int mb = mbase + (mt + 1) * BM;
            #pragma unroll
            for (int t = 0; t < 4; t++) {
                int idx = tid + t * 256;
                int m = idx >> 3, c16 = idx & 7;
                cp_async16(a_nxt + (m * ASTRH + c16 * 8) * 2,
                           &g_merged_h[(mb + m) * COUT + c16 * 8]);
            }
            cp_commit();
        }

        uint32_t a_cur = (mt & 1) ? a_s1 : a_s0;
        uint32_t a_base = a_cur + ((wm + lrow) * ASTRH + lhalf * 8) * 2;

        float acc[4][4][4];
        #pragma unroll
        for (int mf = 0; mf < 4; mf++)
            #pragma unroll
            for (int nf = 0; nf < 4; nf++)
                #pragma unroll
                for (int q = 0; q < 4; q++) acc[mf][nf][q] = 0.f;

        #pragma unroll
        for (int ks = 0; ks < 4; ks++) {
            uint32_t a[4][4], bfr[4][2];
            #pragma unroll
            for (int mf = 0; mf < 4; mf++)
                ldsm_x4(a[mf], a_base + mf * 16 * (ASTRH * 2) + ks * 32);
            #pragma unroll
            for (int nf = 0; nf < 4; nf++)
                ldsm_x2t(bfr[nf], b_base + ks * 16 * (BSTRH * 2) + nf * 16);
            #pragma unroll
            for (int nf = 0; nf < 4; nf++)
                #pragma unroll
                for (int mf = 0; mf < 4; mf++)
                    mma_f16(acc[mf][nf], a[mf], bfr[nf]);
        }

        int m0 = mbase + mt * BM;
        #pragma unroll
        for (int mf = 0; mf < 4; mf++) {
            size_t r0 = (size_t)(m0 + wm + mf * 16 + g) * HW + n0;
            #pragma unroll
            for (int nf = 0; nf < 4; nf++) {
                int col = wn + nf * 8 + 2 * c4;
                *(float2*)&out[r0 + col]          = make_float2(acc[mf][nf][0], acc[mf][nf][1]);
                *(float2*)&out[r0 + 8 * HW + col] = make_float2(acc[mf][nf][2], acc[mf][nf][3]);
            }
        }
    }
}

// ---------------------------------------------------------------------------
extern "C" void kernel_launch(void* const* d_in, const int* in_sizes, int n_in,
                              void* d_out, int out_size)
{
    const float* x        = (const float*)d_in[0];
    const float* idx_feat = (const float*)d_in[1];
    const int*   cate     = (const int*)  d_in[2];
    const float* score    = (const float*)d_in[3];
    const float* W        = (const float*)d_in[4];
    const float* b        = (const float*)d_in[5];
    float* out = (float*)d_out;

    static bool attr_set = false;
    if (!attr_set) {
        cudaFuncSetAttribute(k_mw,    cudaFuncAttributeMaxDynamicSharedMemorySize, MW_SMEM);
        cudaFuncSetAttribute(k_label, cudaFuncAttributeMaxDynamicSharedMemorySize, LB_SMEM);
        attr_set = true;
    }

    k_mw<<<KINST / MWI, 256, MW_SMEM>>>(idx_feat, W, b);
    k_label<<<KINST / TI, 256, LB_SMEM>>>(cate);
    k_pos2_xh<<<POS2_BLOCKS + XH_BLOCKS, 256>>>(x);
    k_merged_tail<<<KINST + 4, 256>>>(cate, score, out);

    dim3 grid(HW / BN, KINST / (MTILES * BM));   // (625, 4)
    k_inst_mma<<<grid, 256>>>(out);
}